// round 1
// baseline (speedup 1.0000x reference)
#include <cuda_runtime.h>
#include <cstdint>

#define H 256
#define W 256
#define K 512
#define Z_THRESHOLD 3.0f
#define EPS 1e-08f

// Sorted gaussian parameter scratch (device globals: no allocation allowed)
__device__ float g_px[K];
__device__ float g_py[K];
__device__ float g_isx[K];
__device__ float g_isy[K];
__device__ float g_w[K];
__device__ float g_int[K];
__device__ int   g_M;

// ---------------------------------------------------------------------------
// Kernel 1: compute eff_w, stable-sort descending by eff_w (bitonic on packed
// uint64 keys), gather parameters in sorted order, count nonzero prefix.
// One block, K threads.
// ---------------------------------------------------------------------------
__global__ void __launch_bounds__(K, 1)
prep_kernel(const float* __restrict__ positions,   // [K,3]
            const float* __restrict__ scales,      // [K,3]
            const float* __restrict__ opacity,     // [K]
            const float* __restrict__ intensity,   // [K]
            const float* __restrict__ z_target)    // [1]
{
    const int tid = threadIdx.x;

    const float zt = z_target[0];
    const float pz = positions[tid * 3 + 2];
    const float sz = scales[tid * 3 + 2];
    const float zd = (zt - pz) / (sz + EPS);
    float w = 0.0f;
    if (fabsf(zd) < Z_THRESHOLD) {
        w = opacity[tid] * __expf(-0.5f * zd * zd);
    }

    // Pack: ascending uint64 sort == descending eff_w, ascending idx on ties.
    // eff_w >= 0 so float bits are monotone; invert for descending.
    unsigned int wb = __float_as_uint(w);
    unsigned long long key =
        ((unsigned long long)(~wb) << 32) | (unsigned int)tid;

    __shared__ unsigned long long sk[K];
    sk[tid] = key;
    __syncthreads();

    // Bitonic sort, ascending.
    for (int k = 2; k <= K; k <<= 1) {
        for (int j = k >> 1; j > 0; j >>= 1) {
            int ixj = tid ^ j;
            if (ixj > tid) {
                unsigned long long a = sk[tid];
                unsigned long long b = sk[ixj];
                bool up = ((tid & k) == 0);
                if ((a > b) == up) {  // out of order for this direction
                    sk[tid] = b;
                    sk[ixj] = a;
                }
            }
            __syncthreads();
        }
    }

    unsigned long long me = sk[tid];
    int src = (int)(me & 0xFFFFFFFFull);
    float wsorted = __uint_as_float(~(unsigned int)(me >> 32));

    g_px[tid]  = positions[src * 3 + 0];
    g_py[tid]  = positions[src * 3 + 1];
    g_isx[tid] = 1.0f / (scales[src * 3 + 0] + EPS);
    g_isy[tid] = 1.0f / (scales[src * 3 + 1] + EPS);
    g_w[tid]   = wsorted;
    g_int[tid] = intensity[src];

    // Count nonzero-weight prefix (zeros sorted to the end; they are
    // compositing identities so the renderer can stop at M).
    int cnt = __syncthreads_count(wsorted > 0.0f);
    if (tid == 0) g_M = cnt;
}

// ---------------------------------------------------------------------------
// Kernel 2: per-pixel front-to-back compositing over the M active gaussians
// in sorted order. Gaussian params staged in shared (broadcast reads).
// ---------------------------------------------------------------------------
__global__ void __launch_bounds__(256)
render_kernel(float* __restrict__ out)
{
    __shared__ float spx[K], spy[K], sisx[K], sisy[K], sw[K], si[K];

    const int tid = threadIdx.x;
    const int M = g_M;

    for (int i = tid; i < M; i += 256) {
        spx[i]  = g_px[i];
        spy[i]  = g_py[i];
        sisx[i] = g_isx[i];
        sisy[i] = g_isy[i];
        sw[i]   = g_w[i];
        si[i]   = g_int[i];
    }
    __syncthreads();

    const int p  = blockIdx.x * 256 + tid;
    const float fy = (float)(p >> 8);   // row    (pairs with positions[:,0])
    const float fx = (float)(p & 255);  // column (pairs with positions[:,1])

    float T = 1.0f;
    float acc = 0.0f;

    #pragma unroll 4
    for (int j = 0; j < M; ++j) {
        float dx = (fy - spx[j]) * sisx[j];
        float dy = (fx - spy[j]) * sisy[j];
        float g  = __expf(-0.5f * (dx * dx + dy * dy));
        float a  = fminf(g * sw[j], 0.99f);
        acc = fmaf(T * a, si[j], acc);
        T *= (1.0f - a);
    }

    out[p] = acc;
}

extern "C" void kernel_launch(void* const* d_in, const int* in_sizes, int n_in,
                              void* d_out, int out_size)
{
    const float* positions = (const float*)d_in[0];
    const float* scales    = (const float*)d_in[1];
    const float* opacity   = (const float*)d_in[2];
    const float* intensity = (const float*)d_in[3];
    const float* z_target  = (const float*)d_in[4];
    float* out = (float*)d_out;

    prep_kernel<<<1, K>>>(positions, scales, opacity, intensity, z_target);
    render_kernel<<<(H * W) / 256, 256>>>(out);
}

// round 2
// speedup vs baseline: 1.4060x; 1.4060x over previous
#include <cuda_runtime.h>
#include <cstdint>

#define H 256
#define W 256
#define K 512
#define Z_THRESHOLD 3.0f
#define EPS 1e-08f

// sqrt(0.5 * log2(e)): folded into inverse scales so gauss = exp2(-(dx'^2+dy'^2))
#define SCALE_C 0.84932180028801904f

// Sorted gaussian parameter scratch (device globals: no allocation allowed)
__device__ float4 g_pack4[K];  // px, py, isx*C, isy*C
__device__ float2 g_pack2[K];  // eff_w, intensity
__device__ int    g_M;

// ---------------------------------------------------------------------------
// Kernel 1: compute eff_w, stable-sort descending by eff_w (register bitonic:
// shuffles for j<32, smem only for the 10 cross-warp phases), pack params in
// sorted order, count nonzero prefix. One block, K threads.
// ---------------------------------------------------------------------------
__global__ void __launch_bounds__(K, 1)
prep_kernel(const float* __restrict__ positions,   // [K,3]
            const float* __restrict__ scales,      // [K,3]
            const float* __restrict__ opacity,     // [K]
            const float* __restrict__ intensity,   // [K]
            const float* __restrict__ z_target)    // [1]
{
    const int tid = threadIdx.x;

    const float zt = z_target[0];
    const float pz = positions[tid * 3 + 2];
    const float sz = scales[tid * 3 + 2];
    const float zd = (zt - pz) / (sz + EPS);
    float w = 0.0f;
    if (fabsf(zd) < Z_THRESHOLD) {
        w = opacity[tid] * __expf(-0.5f * zd * zd);
    }

    // Pack: ascending uint64 sort == descending eff_w, ascending idx on ties
    // (matches stable jnp.argsort(-eff_w); keys unique via embedded idx).
    unsigned int wb = __float_as_uint(w);   // w >= 0 so bits are monotone
    unsigned long long key =
        ((unsigned long long)(~wb) << 32) | (unsigned int)tid;

    __shared__ unsigned long long sk[K];

    // Bitonic sort, ascending, register-resident.
    for (int k = 2; k <= K; k <<= 1) {
        for (int j = k >> 1; j > 0; j >>= 1) {
            unsigned long long b;
            if (j >= 32) {
                sk[tid] = key;
                __syncthreads();
                b = sk[tid ^ j];
                __syncthreads();
            } else {
                b = __shfl_xor_sync(0xFFFFFFFFu, key, j);
            }
            bool up      = ((tid & k) == 0);
            bool lower   = ((tid & j) == 0);
            bool keepMin = (up == lower);
            key = ((key < b) == keepMin) ? key : b;
        }
    }

    int src = (int)(key & 0xFFFFFFFFull);
    float wsorted = __uint_as_float(~(unsigned int)(key >> 32));

    float4 p4;
    p4.x = positions[src * 3 + 0];
    p4.y = positions[src * 3 + 1];
    p4.z = SCALE_C / (scales[src * 3 + 0] + EPS);
    p4.w = SCALE_C / (scales[src * 3 + 1] + EPS);
    g_pack4[tid] = p4;
    g_pack2[tid] = make_float2(wsorted, intensity[src]);

    // Zeros sort to the end and are compositing identities; renderer stops at M.
    int cnt = __syncthreads_count(wsorted > 0.0f);
    if (tid == 0) g_M = cnt;
}

// ---------------------------------------------------------------------------
// Kernel 2: 2 pixels per thread (same row -> shared dx), front-to-back
// compositing over M sorted gaussians. One block per image row.
// ---------------------------------------------------------------------------
__global__ void __launch_bounds__(128)
render_kernel(float* __restrict__ out)
{
    __shared__ float4 sp[K];
    __shared__ float2 swi[K];

    const int tid = threadIdx.x;
    const int M = g_M;

    for (int i = tid; i < M; i += 128) {
        sp[i]  = g_pack4[i];
        swi[i] = g_pack2[i];
    }
    __syncthreads();

    const float fy  = (float)blockIdx.x;          // row (positions[:,0])
    const float fx0 = (float)(2 * tid);           // col (positions[:,1])

    float T0 = 1.0f, T1 = 1.0f;
    float acc0 = 0.0f, acc1 = 0.0f;

    #pragma unroll 4
    for (int j = 0; j < M; ++j) {
        const float4 P  = sp[j];
        const float2 WI = swi[j];

        float dx   = (fy - P.x) * P.z;
        float ndx2 = -dx * dx;
        float dy0  = (fx0 - P.y) * P.w;
        float dy1  = dy0 + P.w;                   // fx1 = fx0 + 1

        float arg0 = fmaf(dy0, -dy0, ndx2);       // -(dx'^2 + dy'^2)
        float arg1 = fmaf(dy1, -dy1, ndx2);

        float g0, g1;
        asm("ex2.approx.ftz.f32 %0, %1;" : "=f"(g0) : "f"(arg0));
        asm("ex2.approx.ftz.f32 %0, %1;" : "=f"(g1) : "f"(arg1));

        float a0 = fminf(g0 * WI.x, 0.99f);
        float a1 = fminf(g1 * WI.x, 0.99f);

        float ta0 = T0 * a0;
        float ta1 = T1 * a1;
        acc0 = fmaf(ta0, WI.y, acc0);
        acc1 = fmaf(ta1, WI.y, acc1);
        T0 -= ta0;
        T1 -= ta1;
    }

    ((float2*)out)[blockIdx.x * 128 + tid] = make_float2(acc0, acc1);
}

extern "C" void kernel_launch(void* const* d_in, const int* in_sizes, int n_in,
                              void* d_out, int out_size)
{
    const float* positions = (const float*)d_in[0];
    const float* scales    = (const float*)d_in[1];
    const float* opacity   = (const float*)d_in[2];
    const float* intensity = (const float*)d_in[3];
    const float* z_target  = (const float*)d_in[4];
    float* out = (float*)d_out;

    prep_kernel<<<1, K>>>(positions, scales, opacity, intensity, z_target);
    render_kernel<<<H, 128>>>(out);
}